// round 5
// baseline (speedup 1.0000x reference)
#include <cuda_runtime.h>
#include <cuda_fp16.h>
#include <stdint.h>
#include <math.h>

#define TOK 2048
#define HID 1024
#define NEXP 8
#define INTER 4096
#define SOFTCAP 30.0f

// ---------------------------------------------------------------------------
// Device-global scratch
// ---------------------------------------------------------------------------
__device__ int    g_cnt[NEXP];
__device__ int    g_list[NEXP][TOK];
__device__ int    g_tpair[TOK * 2];
__device__ float  g_tw[TOK * 2];

__device__ __half g_xh[TOK * HID];
__device__ __half g_acth[(size_t)NEXP * TOK * INTER];
__device__ float  g_pairout[(size_t)NEXP * TOK * HID];

// ---------------------------------------------------------------------------
// PTX helpers (baseline ISA, valid on plain sm_103 target)
// ---------------------------------------------------------------------------
__device__ __forceinline__ uint32_t smem_u32(const void* p) {
    uint32_t a;
    asm("{ .reg .u64 t; cvta.to.shared.u64 t, %1; cvt.u32.u64 %0, t; }"
        : "=r"(a) : "l"(p));
    return a;
}

__device__ __forceinline__ void cpasync16(uint32_t smem, const void* g) {
    asm volatile("cp.async.cg.shared.global [%0], [%1], 16;"
                 :: "r"(smem), "l"(g) : "memory");
}
#define CP_COMMIT() asm volatile("cp.async.commit_group;" ::: "memory")
#define CP_WAIT(n)  asm volatile("cp.async.wait_group %0;" :: "n"(n) : "memory")

__device__ __forceinline__ void ldsm4(uint32_t* r, uint32_t addr) {
    asm volatile("ldmatrix.sync.aligned.m8n8.x4.shared.b16 {%0,%1,%2,%3}, [%4];"
                 : "=r"(r[0]), "=r"(r[1]), "=r"(r[2]), "=r"(r[3]) : "r"(addr));
}

__device__ __forceinline__ void mma16816(float* d, const uint32_t* a,
                                         const uint32_t* b) {
    asm volatile(
        "mma.sync.aligned.m16n8k16.row.col.f32.f16.f16.f32 "
        "{%0,%1,%2,%3}, {%4,%5,%6,%7}, {%8,%9}, {%0,%1,%2,%3};"
        : "+f"(d[0]), "+f"(d[1]), "+f"(d[2]), "+f"(d[3])
        : "r"(a[0]), "r"(a[1]), "r"(a[2]), "r"(a[3]), "r"(b[0]), "r"(b[1]));
}

// pack 8 f32 (two float4) into 4 half2 (uint4) for one 16B swizzled STS
__device__ __forceinline__ uint4 pack8(float4 a, float4 b) {
    __half2 h0 = __floats2half2_rn(a.x, a.y);
    __half2 h1 = __floats2half2_rn(a.z, a.w);
    __half2 h2 = __floats2half2_rn(b.x, b.y);
    __half2 h3 = __floats2half2_rn(b.z, b.w);
    uint4 u;
    u.x = *(uint32_t*)&h0; u.y = *(uint32_t*)&h1;
    u.z = *(uint32_t*)&h2; u.w = *(uint32_t*)&h3;
    return u;
}

// ---------------------------------------------------------------------------
// fp32 -> fp16 (x only; weights are converted inside the GEMMs)
// ---------------------------------------------------------------------------
__global__ void k_tohalf(const float4* __restrict__ in,
                         __half* __restrict__ out, int n4) {
    int i = blockIdx.x * blockDim.x + threadIdx.x;
    if (i >= n4) return;
    float4 v = in[i];
    __half2 h0 = __floats2half2_rn(v.x, v.y);
    __half2 h1 = __floats2half2_rn(v.z, v.w);
    uint2 u;
    u.x = *(uint32_t*)&h0;
    u.y = *(uint32_t*)&h1;
    *(uint2*)(out + (size_t)i * 4) = u;
}

__global__ void k_init() {
    if (threadIdx.x < NEXP) g_cnt[threadIdx.x] = 0;
}

// ---------------------------------------------------------------------------
// Router
// ---------------------------------------------------------------------------
__global__ void k_router(const float* __restrict__ x, const float* __restrict__ wg) {
    const int t = blockIdx.x;
    const float* xr = x + (size_t)t * HID;

    float acc[NEXP];
#pragma unroll
    for (int e = 0; e < NEXP; e++) acc[e] = 0.0f;

    for (int h = threadIdx.x; h < HID; h += 128) {
        float xv = xr[h];
#pragma unroll
        for (int e = 0; e < NEXP; e++)
            acc[e] = fmaf(xv, wg[e * HID + h], acc[e]);
    }
#pragma unroll
    for (int o = 16; o > 0; o >>= 1) {
#pragma unroll
        for (int e = 0; e < NEXP; e++)
            acc[e] += __shfl_down_sync(0xffffffffu, acc[e], o);
    }

    __shared__ float red[4][NEXP];
    int wid = threadIdx.x >> 5;
    int lane = threadIdx.x & 31;
    if (lane == 0) {
#pragma unroll
        for (int e = 0; e < NEXP; e++) red[wid][e] = acc[e];
    }
    __syncthreads();

    if (threadIdx.x == 0) {
        float l[NEXP];
#pragma unroll
        for (int e = 0; e < NEXP; e++) {
            float v = red[0][e] + red[1][e] + red[2][e] + red[3][e];
            l[e] = SOFTCAP * tanhf(v * (1.0f / SOFTCAP));
        }
        int i0 = 0;
#pragma unroll
        for (int e = 1; e < NEXP; e++)
            if (l[e] > l[i0]) i0 = e;
        int i1 = (i0 == 0) ? 1 : 0;
#pragma unroll
        for (int e = 0; e < NEXP; e++)
            if (e != i0 && l[e] > l[i1]) i1 = e;

        float m = l[i0];
        float e0 = expf(l[i0] - m);
        float e1 = expf(l[i1] - m);
        float inv = 1.0f / (e0 + e1);

        int p0 = atomicAdd(&g_cnt[i0], 1);
        g_list[i0][p0] = t;
        int p1 = atomicAdd(&g_cnt[i1], 1);
        g_list[i1][p1] = t;

        g_tpair[t * 2 + 0] = i0 * TOK + p0;
        g_tpair[t * 2 + 1] = i1 * TOK + p1;
        g_tw[t * 2 + 0] = e0 * inv;
        g_tw[t * 2 + 1] = e1 * inv;
    }
}

// ---------------------------------------------------------------------------
// Fused gate+up GEMM: h1 = X@w1^T, h3 = X@w3^T, act = gelu(h1)*h3 -> fp16
// CTA tile 128(M) x 64(N), K-chunk 64 over HID (16 chunks).
// A: fp16 gathered rows, cp.async double-buffered.
// B: f32 weights, LDG->cvt->STS, register double-buffered.
// 8 warps as 2m x 4n, warp tile 64x16 per output.
// ---------------------------------------------------------------------------
#define G13_SMEM (1024 + 32768 + 32768)

__global__ void __launch_bounds__(256) k_g13(const __half* __restrict__ Xh,
                                             const float* __restrict__ W1,
                                             const float* __restrict__ W3) {
    extern __shared__ char smem[];
    const uint32_t sb = smem_u32(smem);
    int* rows_s = (int*)smem;

    const int e = blockIdx.z;
    const int cnt = g_cnt[e];
    const int m0 = blockIdx.x * 128;
    if (m0 >= cnt) return;
    const int n0 = blockIdx.y * 64;

    const int tid = threadIdx.x;
    if (tid < 128) {
        int m = m0 + tid;
        rows_s[tid] = g_list[e][m < cnt ? m : cnt - 1];
    }
    __syncthreads();

    const uint32_t sA = sb + 1024;           // 2 x 16KB
    const uint32_t sB1 = sb + 1024 + 32768;  // 2 x 8KB
    const uint32_t sB3 = sB1 + 16384;        // 2 x 8KB

    // A cp.async slots: 4 x 16B per thread
    size_t arow[4];
    uint32_t aoff[4];
#pragma unroll
    for (int i = 0; i < 4; i++) {
        int lin = tid + 256 * i;
        int r = lin >> 3;
        int kc = lin & 7;
        aoff[i] = ((uint32_t)r << 7) | (((uint32_t)kc << 4) ^ (((uint32_t)(r & 7)) << 4));
        arow[i] = (size_t)rows_s[r] * HID + kc * 8;
    }
    // B slots: 2 pairs per thread per operand (64 rows x 8 chunks = 512 pairs)
    size_t brow1[2], brow3[2];
    uint32_t boff[2];
#pragma unroll
    for (int s = 0; s < 2; s++) {
        int p = tid + 256 * s;
        int r = p >> 3;
        int kc = p & 7;
        boff[s] = ((uint32_t)r << 7) | (((uint32_t)kc << 4) ^ (((uint32_t)(r & 7)) << 4));
        size_t off = ((size_t)e * INTER + n0 + r) * HID + kc * 8;
        brow1[s] = off;
        brow3[s] = off;
    }

    const int lane = tid & 31;
    const int w = tid >> 5;
    const int mw = (w >> 2) * 64;   // 0 or 64
    const int nw = (w & 3) * 16;    // 0,16,32,48

    float acc1[4][2][4], acc3[4][2][4];
#pragma unroll
    for (int mi = 0; mi < 4; mi++)
#pragma unroll
        for (int nj = 0; nj < 2; nj++)
#pragma unroll
            for (int q = 0; q < 4; q++) { acc1[mi][nj][q] = 0.0f; acc3[mi][nj][q] = 0.0f; }

    // prologue: A chunk 0 via cp.async; B chunk 0 into regs
#pragma unroll
    for (int i = 0; i < 4; i++) cpasync16(sA + aoff[i], Xh + arow[i]);
    CP_COMMIT();
    float4 rb1[2][2], rb3[2][2];
#pragma unroll
    for (int s = 0; s < 2; s++) {
        rb1[s][0] = *(const float4*)(W1 + brow1[s]);
        rb1[s][1] = *(const float4*)(W1 + brow1[s] + 4);
        rb3[s][0] = *(const float4*)(W3 + brow3[s]);
        rb3[s][1] = *(const float4*)(W3 + brow3[s] + 4);
    }

    const int nch = HID / 64;  // 16
    for (int it = 0; it < nch; it++) {
        const uint32_t stg = (it & 1) ? 8192u : 0u;
        const uint32_t stgA = (it & 1) ? 16384u : 0u;
        // store B(it) regs -> f16 smem
#pragma unroll
        for (int s = 0; s < 2; s++) {
            *(uint4*)(smem + (sB1 - sb) + stg + boff[s]) = pack8(rb1[s][0], rb1[s][1]);
            *(uint4*)(smem + (sB3 - sb) + stg + boff[s]) = pack8(rb3[s][0], rb3[s][1]);
        }
        // prefetch A(it+1)
        if (it + 1 < nch) {
            const uint32_t nstgA = ((it + 1) & 1) ? 16384u : 0u;
            const int k0 = (it + 1) << 6;
#pragma unroll
            for (int i = 0; i < 4; i++)
                cpasync16(sA + nstgA + aoff[i], Xh + arow[i] + k0);
        }
        CP_COMMIT();
        // prefetch B(it+1) f32 into regs
        if (it + 1 < nch) {
            const int k0 = (it + 1) << 6;
#pragma unroll
            for (int s = 0; s < 2; s++) {
                rb1[s][0] = *(const float4*)(W1 + brow1[s] + k0);
                rb1[s][1] = *(const float4*)(W1 + brow1[s] + k0 + 4);
                rb3[s][0] = *(const float4*)(W3 + brow3[s] + k0);
                rb3[s][1] = *(const float4*)(W3 + brow3[s] + k0 + 4);
            }
        }
        CP_WAIT(1);
        __syncthreads();

        const uint32_t aB = sA + stgA;
        const uint32_t b1B = sB1 + stg;
        const uint32_t b3B = sB3 + stg;
        const int mat = lane >> 3;

#pragma unroll
        for (int kk = 0; kk < 4; kk++) {
            uint32_t af[4][4];
#pragma unroll
            for (int mi = 0; mi < 4; mi++) {
                int row = mw + mi * 16 + (lane & 7) + (mat & 1) * 8;
                int kb = kk * 32 + (mat >> 1) * 16;
                uint32_t so = ((uint32_t)row << 7) |
                              ((uint32_t)kb ^ (((uint32_t)(row & 7)) << 4));
                ldsm4(af[mi], aB + so);
            }
            int brw = nw + (mat >> 1) * 8 + (lane & 7);
            int bkb = kk * 32 + (mat & 1) * 16;
            uint32_t bso = ((uint32_t)brw << 7) |
                           ((uint32_t)bkb ^ (((uint32_t)(brw & 7)) << 4));
            uint32_t bf1[4], bf3[4];
            ldsm4(bf1, b1B + bso);
            ldsm4(bf3, b3B + bso);
#pragma unroll
            for (int mi = 0; mi < 4; mi++) {
                mma16816(acc1[mi][0], af[mi], bf1 + 0);
                mma16816(acc1[mi][1], af[mi], bf1 + 2);
                mma16816(acc3[mi][0], af[mi], bf3 + 0);
                mma16816(acc3[mi][1], af[mi], bf3 + 2);
            }
        }
        __syncthreads();
    }

    // epilogue: act = gelu(h1) * h3 -> fp16, compact rows
#pragma unroll
    for (int mi = 0; mi < 4; mi++) {
        int m1 = m0 + mw + mi * 16 + (lane >> 2);
#pragma unroll
        for (int nj = 0; nj < 2; nj++) {
            int n = n0 + nw + nj * 8 + (lane & 3) * 2;
            __half* op = g_acth + ((size_t)e * TOK + m1) * INTER + n;
            if (m1 < cnt) {
                float a0 = acc1[mi][nj][0], a1 = acc1[mi][nj][1];
                float v0 = 0.5f * a0 * (1.0f + erff(a0 * 0.70710678118654752f)) * acc3[mi][nj][0];
                float v1 = 0.5f * a1 * (1.0f + erff(a1 * 0.70710678118654752f)) * acc3[mi][nj][1];
                *(__half2*)op = __floats2half2_rn(v0, v1);
            }
            if (m1 + 8 < cnt) {
                float a2 = acc1[mi][nj][2], a3 = acc1[mi][nj][3];
                float v2 = 0.5f * a2 * (1.0f + erff(a2 * 0.70710678118654752f)) * acc3[mi][nj][2];
                float v3 = 0.5f * a3 * (1.0f + erff(a3 * 0.70710678118654752f)) * acc3[mi][nj][3];
                *(__half2*)(op + (size_t)8 * INTER) = __floats2half2_rn(v2, v3);
            }
        }
    }
}

// ---------------------------------------------------------------------------
// GEMM2: pairout = act @ w2^T. CTA tile 128x64, K=INTER (64 chunks).
// A: fp16 compact (cp.async), B: f32 w2 convert-on-load.
// ---------------------------------------------------------------------------
#define G2_SMEM (1024 + 32768 + 16384)

__global__ void __launch_bounds__(256) k_g2(const float* __restrict__ W2) {
    extern __shared__ char smem[];
    const uint32_t sb = smem_u32(smem);

    const int e = blockIdx.z;
    const int cnt = g_cnt[e];
    const int m0 = blockIdx.x * 128;
    if (m0 >= cnt) return;
    const int n0 = blockIdx.y * 64;

    const int tid = threadIdx.x;
    const uint32_t sA = sb + 1024;          // 2 x 16KB
    const uint32_t sB = sb + 1024 + 32768;  // 2 x 8KB

    size_t arow[4];
    uint32_t aoff[4];
#pragma unroll
    for (int i = 0; i < 4; i++) {
        int lin = tid + 256 * i;
        int r = lin >> 3;
        int kc = lin & 7;
        aoff[i] = ((uint32_t)r << 7) | (((uint32_t)kc << 4) ^ (((uint32_t)(r & 7)) << 4));
        arow[i] = ((size_t)e * TOK + m0 + r) * INTER + kc * 8;
    }
    size_t brow[2];
    uint32_t boff[2];
#pragma unroll
    for (int s = 0; s < 2; s++) {
        int p = tid + 256 * s;
        int r = p >> 3;
        int kc = p & 7;
        boff[s] = ((uint32_t)r << 7) | (((uint32_t)kc << 4) ^ (((uint32_t)(r & 7)) << 4));
        brow[s] = ((size_t)e * HID + n0 + r) * INTER + kc * 8;
    }

    const int lane = tid & 31;
    const int w = tid >> 5;
    const int mw = (w >> 2) * 64;
    const int nw = (w & 3) * 16;

    float acc[4][2][4];
#pragma unroll
    for (int mi = 0; mi < 4; mi++)
#pragma unroll
        for (int nj = 0; nj < 2; nj++)
#pragma unroll
            for (int q = 0; q < 4; q++) acc[mi][nj][q] = 0.0f;

#pragma unroll
    for (int i = 0; i < 4; i++) cpasync16(sA + aoff[i], g_acth + arow[i]);
    CP_COMMIT();
    float4 rb[2][2];
#pragma unroll
    for (int s = 0; s < 2; s++) {
        rb[s][0] = *(const float4*)(W2 + brow[s]);
        rb[s][1] = *(const float4*)(W2 + brow[s] + 4);
    }

    const int nch = INTER / 64;  // 64
    for (int it = 0; it < nch; it++) {
        const uint32_t stg = (it & 1) ? 8192u : 0u;
        const uint32_t stgA = (it & 1) ? 16384u : 0u;
#pragma unroll
        for (int s = 0; s < 2; s++)
            *(uint4*)(smem + (sB - sb) + stg + boff[s]) = pack8(rb[s][0], rb[s][1]);
        if (it + 1 < nch) {
            const uint32_t nstgA = ((it + 1) & 1) ? 16384u : 0u;
            const int k0 = (it + 1) << 6;
#pragma unroll
            for (int i = 0; i < 4; i++)
                cpasync16(sA + nstgA + aoff[i], g_acth + arow[i] + k0);
        }
        CP_COMMIT();
        if (it + 1 < nch) {
            const int k0 = (it + 1) << 6;
#pragma unroll
            for (int s = 0; s < 2; s++) {
                rb[s][0] = *(const float4*)(W2 + brow[s] + k0);
                rb[s][1] = *(const float4*)(W2 + brow[s] + k0 + 4);
            }
        }
        CP_WAIT(1);
        __syncthreads();

        const uint32_t aB = sA + stgA;
        const uint32_t bB = sB + stg;
        const int mat = lane >> 3;

#pragma unroll
        for (int kk = 0; kk < 4; kk++) {
            uint32_t af[4][4];
#pragma unroll
            for (int mi = 0; mi < 4; mi++) {
                int row = mw + mi * 16 + (lane & 7) + (mat & 1) * 8;
                int kb = kk * 32 + (mat >> 1) * 16;
                uint32_t so = ((uint32_t)row << 7) |
                              ((uint32_t)kb ^ (((uint32_t)(row & 7)) << 4));
                ldsm4(af[mi], aB + so);
            }
            int brw = nw + (mat >> 1) * 8 + (lane & 7);
            int bkb = kk * 32 + (mat & 1) * 16;
            uint32_t bso = ((uint32_t)brw << 7) |
                           ((uint32_t)bkb ^ (((uint32_t)(brw & 7)) << 4));
            uint32_t bf[4];
            ldsm4(bf, bB + bso);
#pragma unroll
            for (int mi = 0; mi < 4; mi++) {
                mma16816(acc[mi][0], af[mi], bf + 0);
                mma16816(acc[mi][1], af[mi], bf + 2);
            }
        }
        __syncthreads();
    }

#pragma unroll
    for (int mi = 0; mi < 4; mi++) {
        int m1 = m0 + mw + mi * 16 + (lane >> 2);
#pragma unroll
        for (int nj = 0; nj < 2; nj++) {
            int n = n0 + nw + nj * 8 + (lane & 3) * 2;
            float* cp = g_pairout + ((size_t)e * TOK + m1) * HID + n;
            if (m1 < cnt)
                *(float2*)cp = make_float2(acc[mi][nj][0], acc[mi][nj][1]);
            if (m1 + 8 < cnt)
                *(float2*)(cp + (size_t)8 * HID) =
                    make_float2(acc[mi][nj][2], acc[mi][nj][3]);
        }
    }
}

// ---------------------------------------------------------------------------
// out[t] = w0 * pairout[p0] + w1 * pairout[p1]
// ---------------------------------------------------------------------------
__global__ void k_combine(float* __restrict__ out) {
    int i = blockIdx.x * 256 + threadIdx.x;
    int t = i >> 10;
    int h = i & (HID - 1);
    out[i] = g_tw[t * 2 + 0] * g_pairout[(size_t)g_tpair[t * 2 + 0] * HID + h] +
             g_tw[t * 2 + 1] * g_pairout[(size_t)g_tpair[t * 2 + 1] * HID + h];
}

// ---------------------------------------------------------------------------
// launch
// ---------------------------------------------------------------------------
extern "C" void kernel_launch(void* const* d_in, const int* in_sizes, int n_in,
                              void* d_out, int out_size) {
    const float* x  = (const float*)d_in[0];
    const float* wg = (const float*)d_in[1];
    const float* w1 = (const float*)d_in[2];
    const float* w3 = (const float*)d_in[3];
    const float* w2 = (const float*)d_in[4];
    float* out = (float*)d_out;

    cudaFuncSetAttribute(k_g13, cudaFuncAttributeMaxDynamicSharedMemorySize, G13_SMEM);
    cudaFuncSetAttribute(k_g2, cudaFuncAttributeMaxDynamicSharedMemorySize, G2_SMEM);

    __half* xh;
    cudaGetSymbolAddress((void**)&xh, g_xh);

    k_tohalf<<<(TOK * HID / 4 + 255) / 256, 256>>>((const float4*)x, xh, TOK * HID / 4);
    k_init<<<1, 32>>>();
    k_router<<<TOK, 128>>>(x, wg);

    k_g13<<<dim3(TOK / 128, INTER / 64, NEXP), 256, G13_SMEM>>>(xh, w1, w3);
    k_g2<<<dim3(TOK / 128, HID / 64, NEXP), 256, G2_SMEM>>>(w2);
    k_combine<<<TOK * HID / 256, 256>>>(out);
}

// round 6
// speedup vs baseline: 1.2058x; 1.2058x over previous
#include <cuda_runtime.h>
#include <cuda_fp16.h>
#include <stdint.h>
#include <math.h>

#define TOK 2048
#define HID 1024
#define NEXP 8
#define INTER 4096
#define SOFTCAP 30.0f

// ---------------------------------------------------------------------------
// Device-global scratch
// ---------------------------------------------------------------------------
__device__ int    g_cnt[NEXP];
__device__ int    g_list[NEXP][TOK];
__device__ int    g_tpair[TOK * 2];
__device__ float  g_tw[TOK * 2];

__device__ __half g_xh[TOK * HID];
__device__ __half g_w1h[(size_t)NEXP * INTER * HID];
__device__ __half g_w3h[(size_t)NEXP * INTER * HID];
__device__ __half g_w2h[(size_t)NEXP * HID * INTER];
__device__ __half g_acth[(size_t)NEXP * TOK * INTER];
__device__ float  g_pairout[(size_t)NEXP * TOK * HID];

// ---------------------------------------------------------------------------
// PTX helpers (baseline ISA, valid on plain sm_103 target)
// ---------------------------------------------------------------------------
__device__ __forceinline__ uint32_t smem_u32(const void* p) {
    uint32_t a;
    asm("{ .reg .u64 t; cvta.to.shared.u64 t, %1; cvt.u32.u64 %0, t; }"
        : "=r"(a) : "l"(p));
    return a;
}

__device__ __forceinline__ void cpasync16(uint32_t smem, const void* g) {
    asm volatile("cp.async.cg.shared.global [%0], [%1], 16;"
                 :: "r"(smem), "l"(g) : "memory");
}
#define CP_COMMIT() asm volatile("cp.async.commit_group;" ::: "memory")
#define CP_WAIT(n)  asm volatile("cp.async.wait_group %0;" :: "n"(n) : "memory")

__device__ __forceinline__ void ldsm4(uint32_t* r, uint32_t addr) {
    asm volatile("ldmatrix.sync.aligned.m8n8.x4.shared.b16 {%0,%1,%2,%3}, [%4];"
                 : "=r"(r[0]), "=r"(r[1]), "=r"(r[2]), "=r"(r[3]) : "r"(addr));
}

__device__ __forceinline__ void mma16816(float* d, const uint32_t* a,
                                         const uint32_t* b) {
    asm volatile(
        "mma.sync.aligned.m16n8k16.row.col.f32.f16.f16.f32 "
        "{%0,%1,%2,%3}, {%4,%5,%6,%7}, {%8,%9}, {%0,%1,%2,%3};"
        : "+f"(d[0]), "+f"(d[1]), "+f"(d[2]), "+f"(d[3])
        : "r"(a[0]), "r"(a[1]), "r"(a[2]), "r"(a[3]), "r"(b[0]), "r"(b[1]));
}

// ---------------------------------------------------------------------------
// fp32 -> fp16 streaming conversion
// ---------------------------------------------------------------------------
__global__ void k_tohalf(const float4* __restrict__ in,
                         __half* __restrict__ out, int n4) {
    int i = blockIdx.x * blockDim.x + threadIdx.x;
    if (i >= n4) return;
    float4 v = in[i];
    __half2 h0 = __floats2half2_rn(v.x, v.y);
    __half2 h1 = __floats2half2_rn(v.z, v.w);
    uint2 u;
    u.x = *(uint32_t*)&h0;
    u.y = *(uint32_t*)&h1;
    *(uint2*)(out + (size_t)i * 4) = u;
}

__global__ void k_init() {
    if (threadIdx.x < NEXP) g_cnt[threadIdx.x] = 0;
}

// ---------------------------------------------------------------------------
// Router
// ---------------------------------------------------------------------------
__global__ void k_router(const float* __restrict__ x, const float* __restrict__ wg) {
    const int t = blockIdx.x;
    const float* xr = x + (size_t)t * HID;

    float acc[NEXP];
#pragma unroll
    for (int e = 0; e < NEXP; e++) acc[e] = 0.0f;

    for (int h = threadIdx.x; h < HID; h += 128) {
        float xv = xr[h];
#pragma unroll
        for (int e = 0; e < NEXP; e++)
            acc[e] = fmaf(xv, wg[e * HID + h], acc[e]);
    }
#pragma unroll
    for (int o = 16; o > 0; o >>= 1) {
#pragma unroll
        for (int e = 0; e < NEXP; e++)
            acc[e] += __shfl_down_sync(0xffffffffu, acc[e], o);
    }

    __shared__ float red[4][NEXP];
    int wid = threadIdx.x >> 5;
    int lane = threadIdx.x & 31;
    if (lane == 0) {
#pragma unroll
        for (int e = 0; e < NEXP; e++) red[wid][e] = acc[e];
    }
    __syncthreads();

    if (threadIdx.x == 0) {
        float l[NEXP];
#pragma unroll
        for (int e = 0; e < NEXP; e++) {
            float v = red[0][e] + red[1][e] + red[2][e] + red[3][e];
            l[e] = SOFTCAP * tanhf(v * (1.0f / SOFTCAP));
        }
        int i0 = 0;
#pragma unroll
        for (int e = 1; e < NEXP; e++)
            if (l[e] > l[i0]) i0 = e;
        int i1 = (i0 == 0) ? 1 : 0;
#pragma unroll
        for (int e = 0; e < NEXP; e++)
            if (e != i0 && l[e] > l[i1]) i1 = e;

        float m = l[i0];
        float e0 = expf(l[i0] - m);
        float e1 = expf(l[i1] - m);
        float inv = 1.0f / (e0 + e1);

        int p0 = atomicAdd(&g_cnt[i0], 1);
        g_list[i0][p0] = t;
        int p1 = atomicAdd(&g_cnt[i1], 1);
        g_list[i1][p1] = t;

        g_tpair[t * 2 + 0] = i0 * TOK + p0;
        g_tpair[t * 2 + 1] = i1 * TOK + p1;
        g_tw[t * 2 + 0] = e0 * inv;
        g_tw[t * 2 + 1] = e1 * inv;
    }
}

// ---------------------------------------------------------------------------
// Fused gate+up GEMM (f16 operands): act = gelu(X@w1^T) * (X@w3^T) -> fp16
// CTA tile 128(M) x 64(N), K-chunk 64 over HID, 2-stage cp.async.
// blockIdx.x in [0,16): GEMM m-tiles. blockIdx.x in [16,20): w2 f32->f16
// converter CTAs (overlap the DRAM-bound conversion with the compute wave).
// ---------------------------------------------------------------------------
#define G13_SMEM (1024 + 32768 + 16384 + 16384)
#define MTILES 16
#define CONVX 4

__global__ void __launch_bounds__(256, 2) k_g13(const __half* __restrict__ Xh,
                                                const __half* __restrict__ W1,
                                                const __half* __restrict__ W3,
                                                const float* __restrict__ W2f) {
    extern __shared__ char smem[];
    const int tid = threadIdx.x;

    // ---- converter CTAs: stream w2 f32 -> f16 ----
    if (blockIdx.x >= MTILES) {
        int cid = ((blockIdx.x - MTILES) * gridDim.y + blockIdx.y) * gridDim.z
                  + blockIdx.z;                        // 0 .. 2047
        const int nconv = CONVX * (INTER / 64) * NEXP; // 2048
        const size_t n4 = (size_t)NEXP * HID * INTER / 4;
        size_t i = (size_t)cid * 256 + tid;
        const size_t stride = (size_t)nconv * 256;
        for (; i < n4; i += stride) {
            float4 v = ((const float4*)W2f)[i];
            __half2 h0 = __floats2half2_rn(v.x, v.y);
            __half2 h1 = __floats2half2_rn(v.z, v.w);
            uint2 u;
            u.x = *(uint32_t*)&h0;
            u.y = *(uint32_t*)&h1;
            *(uint2*)(g_w2h + i * 4) = u;
        }
        return;
    }

    const uint32_t sb = smem_u32(smem);
    int* rows_s = (int*)smem;

    const int e = blockIdx.z;
    const int cnt = g_cnt[e];
    const int m0 = blockIdx.x * 128;
    if (m0 >= cnt) return;
    const int n0 = blockIdx.y * 64;

    if (tid < 128) {
        int m = m0 + tid;
        rows_s[tid] = g_list[e][m < cnt ? m : cnt - 1];
    }
    __syncthreads();

    const uint32_t sA = sb + 1024;           // 2 x 16KB
    const uint32_t sB1 = sb + 1024 + 32768;  // 2 x 8KB
    const uint32_t sB3 = sB1 + 16384;        // 2 x 8KB

    size_t arow[4];
    uint32_t aoff[4];
#pragma unroll
    for (int i = 0; i < 4; i++) {
        int lin = tid + 256 * i;
        int r = lin >> 3;
        int kc = lin & 7;
        aoff[i] = ((uint32_t)r << 7) | (((uint32_t)kc << 4) ^ (((uint32_t)(r & 7)) << 4));
        arow[i] = (size_t)rows_s[r] * HID + kc * 8;
    }
    size_t brow[2];
    uint32_t boff[2];
#pragma unroll
    for (int s = 0; s < 2; s++) {
        int p = tid + 256 * s;
        int r = p >> 3;
        int kc = p & 7;
        boff[s] = ((uint32_t)r << 7) | (((uint32_t)kc << 4) ^ (((uint32_t)(r & 7)) << 4));
        brow[s] = ((size_t)e * INTER + n0 + r) * HID + kc * 8;
    }

    const int lane = tid & 31;
    const int w = tid >> 5;
    const int mw = (w >> 2) * 64;   // 0 or 64
    const int nw = (w & 3) * 16;    // 0,16,32,48

    float acc1[4][2][4], acc3[4][2][4];
#pragma unroll
    for (int mi = 0; mi < 4; mi++)
#pragma unroll
        for (int nj = 0; nj < 2; nj++)
#pragma unroll
            for (int q = 0; q < 4; q++) { acc1[mi][nj][q] = 0.0f; acc3[mi][nj][q] = 0.0f; }

#pragma unroll
    for (int i = 0; i < 4; i++) cpasync16(sA + aoff[i], Xh + arow[i]);
#pragma unroll
    for (int s = 0; s < 2; s++) {
        cpasync16(sB1 + boff[s], W1 + brow[s]);
        cpasync16(sB3 + boff[s], W3 + brow[s]);
    }
    CP_COMMIT();

    const int nch = HID / 64;  // 16
    for (int it = 0; it < nch; it++) {
        if (it + 1 < nch) {
            const int k0 = (it + 1) << 6;
            const uint32_t sg = ((it + 1) & 1) ? 1u : 0u;
#pragma unroll
            for (int i = 0; i < 4; i++)
                cpasync16(sA + sg * 16384u + aoff[i], Xh + arow[i] + k0);
#pragma unroll
            for (int s = 0; s < 2; s++) {
                cpasync16(sB1 + sg * 8192u + boff[s], W1 + brow[s] + k0);
                cpasync16(sB3 + sg * 8192u + boff[s], W3 + brow[s] + k0);
            }
            CP_COMMIT();
            CP_WAIT(1);
        } else {
            CP_WAIT(0);
        }
        __syncthreads();

        const uint32_t aB = sA + ((it & 1) ? 16384u : 0u);
        const uint32_t b1B = sB1 + ((it & 1) ? 8192u : 0u);
        const uint32_t b3B = sB3 + ((it & 1) ? 8192u : 0u);
        const int mat = lane >> 3;

#pragma unroll
        for (int kk = 0; kk < 4; kk++) {
            uint32_t af[4][4];
#pragma unroll
            for (int mi = 0; mi < 4; mi++) {
                int row = mw + mi * 16 + (lane & 7) + (mat & 1) * 8;
                int kb = kk * 32 + (mat >> 1) * 16;
                uint32_t so = ((uint32_t)row << 7) |
                              ((uint32_t)kb ^ (((uint32_t)(row & 7)) << 4));
                ldsm4(af[mi], aB + so);
            }
            int brw = nw + (mat >> 1) * 8 + (lane & 7);
            int bkb = kk * 32 + (mat & 1) * 16;
            uint32_t bso = ((uint32_t)brw << 7) |
                           ((uint32_t)bkb ^ (((uint32_t)(brw & 7)) << 4));
            uint32_t bf1[4], bf3[4];
            ldsm4(bf1, b1B + bso);
            ldsm4(bf3, b3B + bso);
#pragma unroll
            for (int mi = 0; mi < 4; mi++) {
                mma16816(acc1[mi][0], af[mi], bf1 + 0);
                mma16816(acc1[mi][1], af[mi], bf1 + 2);
                mma16816(acc3[mi][0], af[mi], bf3 + 0);
                mma16816(acc3[mi][1], af[mi], bf3 + 2);
            }
        }
        __syncthreads();
    }

#pragma unroll
    for (int mi = 0; mi < 4; mi++) {
        int m1 = m0 + mw + mi * 16 + (lane >> 2);
#pragma unroll
        for (int nj = 0; nj < 2; nj++) {
            int n = n0 + nw + nj * 8 + (lane & 3) * 2;
            __half* op = g_acth + ((size_t)e * TOK + m1) * INTER + n;
            if (m1 < cnt) {
                float a0 = acc1[mi][nj][0], a1 = acc1[mi][nj][1];
                float v0 = 0.5f * a0 * (1.0f + erff(a0 * 0.70710678118654752f)) * acc3[mi][nj][0];
                float v1 = 0.5f * a1 * (1.0f + erff(a1 * 0.70710678118654752f)) * acc3[mi][nj][1];
                *(__half2*)op = __floats2half2_rn(v0, v1);
            }
            if (m1 + 8 < cnt) {
                float a2 = acc1[mi][nj][2], a3 = acc1[mi][nj][3];
                float v2 = 0.5f * a2 * (1.0f + erff(a2 * 0.70710678118654752f)) * acc3[mi][nj][2];
                float v3 = 0.5f * a3 * (1.0f + erff(a3 * 0.70710678118654752f)) * acc3[mi][nj][3];
                *(__half2*)(op + (size_t)8 * INTER) = __floats2half2_rn(v2, v3);
            }
        }
    }
}

// ---------------------------------------------------------------------------
// GEMM2: pairout = act @ w2^T (f16 operands). CTA tile 128x64, K=INTER.
// ---------------------------------------------------------------------------
#define G2_SMEM (1024 + 32768 + 16384)

__global__ void __launch_bounds__(256, 3) k_g2(const __half* __restrict__ W2) {
    extern __shared__ char smem[];
    const uint32_t sb = smem_u32(smem);

    const int e = blockIdx.z;
    const int cnt = g_cnt[e];
    const int m0 = blockIdx.x * 128;
    if (m0 >= cnt) return;
    const int n0 = blockIdx.y * 64;

    const int tid = threadIdx.x;
    const uint32_t sA = sb + 1024;
    const uint32_t sB = sb + 1024 + 32768;

    size_t arow[4];
    uint32_t aoff[4];
#pragma unroll
    for (int i = 0; i < 4; i++) {
        int lin = tid + 256 * i;
        int r = lin >> 3;
        int kc = lin & 7;
        aoff[i] = ((uint32_t)r << 7) | (((uint32_t)kc << 4) ^ (((uint32_t)(r & 7)) << 4));
        arow[i] = ((size_t)e * TOK + m0 + r) * INTER + kc * 8;
    }
    size_t brow[2];
    uint32_t boff[2];
#pragma unroll
    for (int s = 0; s < 2; s++) {
        int p = tid + 256 * s;
        int r = p >> 3;
        int kc = p & 7;
        boff[s] = ((uint32_t)r << 7) | (((uint32_t)kc << 4) ^ (((uint32_t)(r & 7)) << 4));
        brow[s] = ((size_t)e * HID + n0 + r) * INTER + kc * 8;
    }

    const int lane = tid & 31;
    const int w = tid >> 5;
    const int mw = (w >> 2) * 64;
    const int nw = (w & 3) * 16;

    float acc[4][2][4];
#pragma unroll
    for (int mi = 0; mi < 4; mi++)
#pragma unroll
        for (int nj = 0; nj < 2; nj++)
#pragma unroll
            for (int q = 0; q < 4; q++) acc[mi][nj][q] = 0.0f;

#pragma unroll
    for (int i = 0; i < 4; i++) cpasync16(sA + aoff[i], g_acth + arow[i]);
#pragma unroll
    for (int s = 0; s < 2; s++) cpasync16(sB + boff[s], W2 + brow[s]);
    CP_COMMIT();

    const int nch = INTER / 64;  // 64
    for (int it = 0; it < nch; it++) {
        if (it + 1 < nch) {
            const int k0 = (it + 1) << 6;
            const uint32_t sg = ((it + 1) & 1) ? 1u : 0u;
#pragma unroll
            for (int i = 0; i < 4; i++)
                cpasync16(sA + sg * 16384u + aoff[i], g_acth + arow[i] + k0);
#pragma unroll
            for (int s = 0; s < 2; s++)
                cpasync16(sB + sg * 8192u + boff[s], W2 + brow[s] + k0);
            CP_COMMIT();
            CP_WAIT(1);
        } else {
            CP_WAIT(0);
        }
        __syncthreads();

        const uint32_t aB = sA + ((it & 1) ? 16384u : 0u);
        const uint32_t bB = sB + ((it & 1) ? 8192u : 0u);
        const int mat = lane >> 3;

#pragma unroll
        for (int kk = 0; kk < 4; kk++) {
            uint32_t af[4][4];
#pragma unroll
            for (int mi = 0; mi < 4; mi++) {
                int row = mw + mi * 16 + (lane & 7) + (mat & 1) * 8;
                int kb = kk * 32 + (mat >> 1) * 16;
                uint32_t so = ((uint32_t)row << 7) |
                              ((uint32_t)kb ^ (((uint32_t)(row & 7)) << 4));
                ldsm4(af[mi], aB + so);
            }
            int brw = nw + (mat >> 1) * 8 + (lane & 7);
            int bkb = kk * 32 + (mat & 1) * 16;
            uint32_t bso = ((uint32_t)brw << 7) |
                           ((uint32_t)bkb ^ (((uint32_t)(brw & 7)) << 4));
            uint32_t bf[4];
            ldsm4(bf, bB + bso);
#pragma unroll
            for (int mi = 0; mi < 4; mi++) {
                mma16816(acc[mi][0], af[mi], bf + 0);
                mma16816(acc[mi][1], af[mi], bf + 2);
            }
        }
        __syncthreads();
    }

#pragma unroll
    for (int mi = 0; mi < 4; mi++) {
        int m1 = m0 + mw + mi * 16 + (lane >> 2);
#pragma unroll
        for (int nj = 0; nj < 2; nj++) {
            int n = n0 + nw + nj * 8 + (lane & 3) * 2;
            float* cp = g_pairout + ((size_t)e * TOK + m1) * HID + n;
            if (m1 < cnt)
                *(float2*)cp = make_float2(acc[mi][nj][0], acc[mi][nj][1]);
            if (m1 + 8 < cnt)
                *(float2*)(cp + (size_t)8 * HID) =
                    make_float2(acc[mi][nj][2], acc[mi][nj][3]);
        }
    }
}

// ---------------------------------------------------------------------------
// out[t] = w0 * pairout[p0] + w1 * pairout[p1]
// ---------------------------------------------------------------------------
__global__ void k_combine(float* __restrict__ out) {
    int i = blockIdx.x * 256 + threadIdx.x;
    int t = i >> 10;
    int h = i & (HID - 1);
    out[i] = g_tw[t * 2 + 0] * g_pairout[(size_t)g_tpair[t * 2 + 0] * HID + h] +
             g_tw[t * 2 + 1] * g_pairout[(size_t)g_tpair[t * 2 + 1] * HID + h];
}

// ---------------------------------------------------------------------------
// launch
// ---------------------------------------------------------------------------
extern "C" void kernel_launch(void* const* d_in, const int* in_sizes, int n_in,
                              void* d_out, int out_size) {
    const float* x  = (const float*)d_in[0];
    const float* wg = (const float*)d_in[1];
    const float* w1 = (const float*)d_in[2];
    const float* w3 = (const float*)d_in[3];
    const float* w2 = (const float*)d_in[4];
    float* out = (float*)d_out;

    cudaFuncSetAttribute(k_g13, cudaFuncAttributeMaxDynamicSharedMemorySize, G13_SMEM);
    cudaFuncSetAttribute(k_g2, cudaFuncAttributeMaxDynamicSharedMemorySize, G2_SMEM);

    __half *xh, *w1h, *w3h, *w2h;
    cudaGetSymbolAddress((void**)&xh, g_xh);
    cudaGetSymbolAddress((void**)&w1h, g_w1h);
    cudaGetSymbolAddress((void**)&w3h, g_w3h);
    cudaGetSymbolAddress((void**)&w2h, g_w2h);

    const int nw4 = (int)((size_t)NEXP * INTER * HID / 4);
    k_tohalf<<<(TOK * HID / 4 + 255) / 256, 256>>>((const float4*)x, xh, TOK * HID / 4);
    k_tohalf<<<(nw4 + 255) / 256, 256>>>((const float4*)w1, w1h, nw4);
    k_tohalf<<<(nw4 + 255) / 256, 256>>>((const float4*)w3, w3h, nw4);

    k_init<<<1, 32>>>();
    k_router<<<TOK, 128>>>(x, wg);

    // x-dim: [0,16) GEMM m-tiles, [16,20) w2 converter CTAs (overlapped)
    k_g13<<<dim3(MTILES + CONVX, INTER / 64, NEXP), 256, G13_SMEM>>>(xh, w1h, w3h, w2);
    k_g2<<<dim3(TOK / 128, HID / 64, NEXP), 256, G2_SMEM>>>(w2h);
    k_combine<<<TOK * HID / 256, 256>>>(out);
}